// round 3
// baseline (speedup 1.0000x reference)
#include <cuda_runtime.h>
#include <math.h>

#define BM 128
#define BN 128
#define BK 16
#define AST 18   // As row stride (words): gcd(18,32)=2 -> conflict-free pair reads

// ---------------- scratch (static device globals; no allocation) ----------------
__device__ __align__(256) float g_tmp [10000 * 512];  // h-hat (widest conv = 512)
__device__ __align__(256) float g_h1  [10000 * 128];
__device__ __align__(256) float g_d1  [10000 * 128];
__device__ __align__(256) float g_hmid[10000 * 128];
__device__ float g_dis[10016];
__device__ int   g_cnt[10016];
__device__ int   g_rowptr[10017];
__device__ int   g_cursor[10016];
__device__ int   g_eidx[320000];

// buffer selector: 0 = external pointer, 1..4 = module-global scratch
__device__ __forceinline__ float* sel_buf(int id, float* ext) {
    switch (id) {
        case 1: return g_tmp;
        case 2: return g_h1;
        case 3: return g_d1;
        case 4: return g_hmid;
        default: return ext;
    }
}

// packed fp32x2 FMA (full-rate fp32 path on sm_103a; plain FFMA-3reg is half rate)
__device__ __forceinline__ void ffma2(float2 &d, const float2 &a, const float2 &b) {
    unsigned long long du = *reinterpret_cast<unsigned long long*>(&d);
    unsigned long long au = *reinterpret_cast<const unsigned long long*>(&a);
    unsigned long long bu = *reinterpret_cast<const unsigned long long*>(&b);
    asm("fma.rn.f32x2 %0, %1, %2, %0;" : "+l"(du) : "l"(au), "l"(bu));
    d = *reinterpret_cast<float2*>(&du);
}

// ---------------- CSR build ----------------
__global__ void zero_kernel(int N) {
    int i = blockIdx.x * blockDim.x + threadIdx.x;
    if (i < N) g_cnt[i] = 0;
}

__global__ void hist_kernel(const int* __restrict__ dst, int E) {
    int e = blockIdx.x * blockDim.x + threadIdx.x;
    if (e < E) atomicAdd(&g_cnt[dst[e]], 1);
}

__global__ void scan_kernel(int N, int E) {
    __shared__ int sums[256];
    int t = threadIdx.x;
    int chunk = (N + 255) >> 8;
    int b0 = t * chunk;
    int b1 = min(b0 + chunk, N);
    int s = 0;
    for (int i = b0; i < b1; i++) s += g_cnt[i];
    sums[t] = s;
    __syncthreads();
    for (int off = 1; off < 256; off <<= 1) {
        int v = sums[t];
        int w = (t >= off) ? sums[t - off] : 0;
        __syncthreads();
        sums[t] = v + w;
        __syncthreads();
    }
    int pref = (t > 0) ? sums[t - 1] : 0;
    for (int i = b0; i < b1; i++) {
        g_rowptr[i] = pref;
        g_cursor[i] = pref;
        g_dis[i]    = rsqrtf((float)g_cnt[i] + 1.0f);  // deg + self loop
        pref += g_cnt[i];
    }
    if (t == 0) g_rowptr[N] = E;
}

__global__ void fill_kernel(const int* __restrict__ src,
                            const int* __restrict__ dst, int E) {
    int e = blockIdx.x * blockDim.x + threadIdx.x;
    if (e < E) {
        int pos = atomicAdd(&g_cursor[dst[e]], 1);
        g_eidx[pos] = src[e];
    }
}

// ---------------- GEMM: C = epilogue(A[M,K] @ B[K,Nc]) ----------------
// MODE 0: out = (A@B) * dis[row]            (GCN pre-aggregation)
// MODE 1: out = relu((A@B) + bias[col])     (link predictor hidden; SQ squares A)
// MODE 2: out = sigmoid((A@B) + bias[col])  (final struct)
template<int MODE, bool SQ>
__global__ __launch_bounds__(256, 1)
void gemm_kernel(const float* __restrict__ Aext, int Aid,
                 const float* __restrict__ B,
                 const float* __restrict__ bias,
                 float* __restrict__ Oext, int Oid,
                 int M, int K, int Nc)
{
    const float* A = sel_buf(Aid, const_cast<float*>(Aext));
    float* out = sel_buf(Oid, Oext);

    __shared__ float As[BM * AST];
    __shared__ float Bs[BK * BN];

    const int tid = threadIdx.x;
    const int tx = tid & 15;   // column group
    const int ty = tid >> 4;   // row group
    const int row0 = blockIdx.y * BM;
    const int col0 = blockIdx.x * BN;

    float2 acc[8][8];
#pragma unroll
    for (int i = 0; i < 8; i++)
#pragma unroll
        for (int j = 0; j < 8; j++) acc[i][j] = make_float2(0.f, 0.f);

    for (int k0 = 0; k0 < K; k0 += BK) {
        // A tile -> As[m][k], stride 18
#pragma unroll
        for (int p = 0; p < 2; p++) {
            int idx = tid + p * 256;       // 0..511
            int r   = idx >> 2;            // 0..127
            int k4  = (idx & 3) << 2;      // 0,4,8,12
            float4 v = make_float4(0.f, 0.f, 0.f, 0.f);
            int gr = row0 + r;
            if (gr < M) v = *reinterpret_cast<const float4*>(A + (size_t)gr * K + (k0 + k4));
            if (SQ) { v.x *= v.x; v.y *= v.y; v.z *= v.z; v.w *= v.w; }
            float* d0 = &As[r * AST + k4];
            d0[0] = v.x; d0[1] = v.y; d0[2] = v.z; d0[3] = v.w;
        }
        // B tile -> Bs[k][n], natural
#pragma unroll
        for (int p = 0; p < 2; p++) {
            int idx = tid + p * 256;
            int kr  = idx >> 5;            // 0..15
            int c4  = (idx & 31) << 2;     // 0..124
            float4 v = make_float4(0.f, 0.f, 0.f, 0.f);
            int gc = col0 + c4;
            if (gc < Nc) v = *reinterpret_cast<const float4*>(B + (size_t)(k0 + kr) * Nc + gc);
            *reinterpret_cast<float4*>(&Bs[kr * BN + c4]) = v;
        }
        __syncthreads();

#pragma unroll
        for (int kp = 0; kp < 8; kp++) {   // k pairs
            float2 a2[8], b2[8];
#pragma unroll
            for (int i = 0; i < 8; i++)
                a2[i] = *reinterpret_cast<const float2*>(&As[(ty + 16 * i) * AST + 2 * kp]);
#pragma unroll
            for (int j = 0; j < 8; j++) {
                b2[j].x = Bs[(2 * kp)     * BN + tx + 16 * j];
                b2[j].y = Bs[(2 * kp + 1) * BN + tx + 16 * j];
            }
#pragma unroll
            for (int i = 0; i < 8; i++)
#pragma unroll
                for (int j = 0; j < 8; j++)
                    ffma2(acc[i][j], a2[i], b2[j]);
        }
        __syncthreads();
    }

    // epilogue
    float bv[8];
    if (MODE != 0) {
#pragma unroll
        for (int j = 0; j < 8; j++) {
            int col = col0 + tx + 16 * j;
            bv[j] = (col < Nc) ? bias[col] : 0.f;
        }
    }
#pragma unroll
    for (int i = 0; i < 8; i++) {
        int row = row0 + ty + 16 * i;
        if (row >= M) continue;
        float scale = (MODE == 0) ? g_dis[row] : 1.f;
        size_t roff = (size_t)row * Nc;
#pragma unroll
        for (int j = 0; j < 8; j++) {
            int col = col0 + tx + 16 * j;
            if (col >= Nc) continue;
            float v = acc[i][j].x + acc[i][j].y;
            if (MODE == 0)      v *= scale;
            else if (MODE == 1) v = fmaxf(v + bv[j], 0.f);
            else { float t = v + bv[j]; v = 1.f / (1.f + __expf(-t)); }
            out[roff + col] = v;
        }
    }
}

// ---------------- GCN aggregation: atomic-free CSR gather + finalize ----------------
// out[n,:] = relu(dis[n] * (g_tmp[n,:] + sum_{src in N(n)} g_tmp[src,:]) + bias)
__global__ void gather_kernel(const float* __restrict__ bias,
                              float* __restrict__ Oext, int Oid,
                              int N, int W, int log2wpn)
{
    float* out = sel_buf(Oid, Oext);
    int gid  = blockIdx.x * blockDim.x + threadIdx.x;
    int gw   = gid >> 5;
    int lane = gid & 31;
    int node = gw >> log2wpn;
    if (node >= N) return;
    int seg = gw & ((1 << log2wpn) - 1);
    int col = (seg << 7) | (lane << 2);

    const float* base = g_tmp + col;
    float4 acc = *reinterpret_cast<const float4*>(base + (size_t)node * W);  // self term
    int p0 = g_rowptr[node], p1 = g_rowptr[node + 1];
    for (int p = p0; p < p1; p++) {
        int s = g_eidx[p];
        float4 v = *reinterpret_cast<const float4*>(base + (size_t)s * W);
        acc.x += v.x; acc.y += v.y; acc.z += v.z; acc.w += v.w;
    }
    float d = g_dis[node];
    float4 b = *reinterpret_cast<const float4*>(bias + col);
    float4 r;
    r.x = fmaxf(fmaf(d, acc.x, b.x), 0.f);
    r.y = fmaxf(fmaf(d, acc.y, b.y), 0.f);
    r.z = fmaxf(fmaf(d, acc.z, b.z), 0.f);
    r.w = fmaxf(fmaf(d, acc.w, b.w), 0.f);
    *reinterpret_cast<float4*>(out + (size_t)node * W + col) = r;
}

// ---------------- launch ----------------
extern "C" void kernel_launch(void* const* d_in, const int* in_sizes, int n_in,
                              void* d_out, int out_size)
{
    const float* x   = (const float*)d_in[0];
    const int*   ei  = (const int*)d_in[1];   // int32 on device (JAX x64 disabled)
    const float* We1 = (const float*)d_in[2];
    const float* be1 = (const float*)d_in[3];
    const float* We2 = (const float*)d_in[4];
    const float* be2 = (const float*)d_in[5];
    const float* Wd1 = (const float*)d_in[6];
    const float* bd1 = (const float*)d_in[7];
    const float* Wd2 = (const float*)d_in[8];
    const float* bd2 = (const float*)d_in[9];
    const float* Wl  = (const float*)d_in[10];
    const float* bl  = (const float*)d_in[11];
    const float* Wf  = (const float*)d_in[12];
    const float* bf  = (const float*)d_in[13];

    const int E = in_sizes[1] / 2;     // edge_index is [2, E]
    const int N = in_sizes[13];        // bf: [N]
    const int F = in_sizes[0] / N;     // x: [N, F]
    const int H = in_sizes[3];         // be1: [H]

    const int* srcp = ei;
    const int* dstp = ei + E;

    float* struct_out = (float*)d_out;                       // [N, N]
    float* xhat_out   = struct_out + (size_t)N * N;          // [N, F]
    float* z_out      = xhat_out + (size_t)N * F;            // [N, H]

    const int tb = 256;
    // CSR (deg/dis) build — shared by all 4 convs
    zero_kernel<<<(N + tb - 1) / tb, tb>>>(N);
    hist_kernel<<<(E + tb - 1) / tb, tb>>>(dstp, E);
    scan_kernel<<<1, 256>>>(N, E);
    fill_kernel<<<(E + tb - 1) / tb, tb>>>(srcp, dstp, E);

    dim3 thr(256);
    auto grid = [](int M, int Nc) { return dim3((Nc + BN - 1) / BN, (M + BM - 1) / BM); };
    int gb128 = (N * 32 + 255) / 256;       // 1 warp / node  (W = 128)
    int gb512 = (N * 4 * 32 + 255) / 256;   // 4 warps / node (W = 512)

    // conv1: x[N,F] @ We1 -> g_tmp -> gather -> g_h1
    gemm_kernel<0, false><<<grid(N, H), thr>>>(x, 0, We1, nullptr, nullptr, 1, N, F, H);
    gather_kernel<<<gb128, 256>>>(be1, nullptr, 2, N, H, 0);
    // conv2: g_h1 @ We2 -> g_tmp -> gather -> z (output)
    gemm_kernel<0, false><<<grid(N, H), thr>>>(nullptr, 2, We2, nullptr, nullptr, 1, N, H, H);
    gather_kernel<<<gb128, 256>>>(be2, z_out, 0, N, H, 0);
    // conv3: z @ Wd1 -> g_tmp -> gather -> g_d1
    gemm_kernel<0, false><<<grid(N, H), thr>>>(z_out, 0, Wd1, nullptr, nullptr, 1, N, H, H);
    gather_kernel<<<gb128, 256>>>(bd1, nullptr, 3, N, H, 0);
    // conv4: g_d1 @ Wd2 -> g_tmp -> gather -> x_hat (output)
    gemm_kernel<0, false><<<grid(N, F), thr>>>(nullptr, 3, Wd2, nullptr, nullptr, 1, N, H, F);
    gather_kernel<<<gb512, 256>>>(bd2, xhat_out, 0, N, F, 2);
    // hmid = relu((x_hat^2) @ Wl + bl) -> g_hmid
    gemm_kernel<1, true><<<grid(N, H), thr>>>(xhat_out, 0, Wl, bl, nullptr, 4, N, F, H);
    // struct = sigmoid(g_hmid @ Wf + bf)   — the big one
    gemm_kernel<2, false><<<grid(N, N), thr>>>(nullptr, 4, Wf, bf, struct_out, 0, N, H, N);
}

// round 5
// speedup vs baseline: 1.5310x; 1.5310x over previous
#include <cuda_runtime.h>
#include <cuda_bf16.h>
#include <math.h>
#include <stdint.h>

#define BN 128
#define BK 16
#define AST 18   // As row stride (words): gcd(18,32)=2 -> conflict-free pair reads

#define APAD_ROWS 10112   // 79 * 128

// ---------------- scratch (static device globals; no allocation) ----------------
__device__ __align__(256) float g_tmp [10000 * 512];  // h-hat (widest conv = 512)
__device__ __align__(256) float g_h1  [10000 * 128];
__device__ __align__(256) float g_d1  [10000 * 128];
__device__ float g_dis[10016];
__device__ int   g_cnt[10016];
__device__ int   g_rowptr[10017];
__device__ int   g_cursor[10016];
__device__ int   g_eidx[320000];
// bf16 hi/lo operands for the tensor-core struct GEMM
__device__ __align__(256) __nv_bfloat16 g_ahi[APAD_ROWS * 128];
__device__ __align__(256) __nv_bfloat16 g_alo[APAD_ROWS * 128];
__device__ __align__(256) __nv_bfloat16 g_bhi[APAD_ROWS * 128];
__device__ __align__(256) __nv_bfloat16 g_blo[APAD_ROWS * 128];

// buffer selector: 0 = external pointer, 1..3 = module-global scratch
__device__ __forceinline__ float* sel_buf(int id, float* ext) {
    switch (id) {
        case 1: return g_tmp;
        case 2: return g_h1;
        case 3: return g_d1;
        default: return ext;
    }
}

// packed fp32x2 FMA (full-rate fp32 path on sm_103a; plain FFMA-3reg is half rate)
__device__ __forceinline__ void ffma2(float2 &d, const float2 &a, const float2 &b) {
    unsigned long long du = *reinterpret_cast<unsigned long long*>(&d);
    unsigned long long au = *reinterpret_cast<const unsigned long long*>(&a);
    unsigned long long bu = *reinterpret_cast<const unsigned long long*>(&b);
    asm("fma.rn.f32x2 %0, %1, %2, %0;" : "+l"(du) : "l"(au), "l"(bu));
    d = *reinterpret_cast<float2*>(&du);
}

__device__ __forceinline__ uint32_t smem_to_u32(const void* p) {
    uint32_t a;
    asm("{ .reg .u64 t; cvta.to.shared.u64 t, %1; cvt.u32.u64 %0, t; }" : "=r"(a) : "l"(p));
    return a;
}

__device__ __forceinline__ void cp_async16(uint32_t dst, const void* src) {
    asm volatile("cp.async.cg.shared.global [%0], [%1], 16;" :: "r"(dst), "l"(src));
}

__device__ __forceinline__ void ldsm4(uint32_t* r, uint32_t addr) {
    asm volatile("ldmatrix.sync.aligned.m8n8.x4.shared.b16 {%0,%1,%2,%3}, [%4];"
                 : "=r"(r[0]), "=r"(r[1]), "=r"(r[2]), "=r"(r[3]) : "r"(addr));
}

__device__ __forceinline__ void mma_bf16(float* d, const uint32_t* a, const uint32_t* b) {
    asm volatile(
        "mma.sync.aligned.m16n8k16.row.col.f32.bf16.bf16.f32 "
        "{%0,%1,%2,%3}, {%4,%5,%6,%7}, {%8,%9}, {%0,%1,%2,%3};"
        : "+f"(d[0]), "+f"(d[1]), "+f"(d[2]), "+f"(d[3])
        : "r"(a[0]), "r"(a[1]), "r"(a[2]), "r"(a[3]), "r"(b[0]), "r"(b[1]));
}

// ---------------- CSR build ----------------
__global__ void zero_kernel(int N) {
    int i = blockIdx.x * blockDim.x + threadIdx.x;
    if (i < N) g_cnt[i] = 0;
}

__global__ void hist_kernel(const int* __restrict__ dst, int E) {
    int e = blockIdx.x * blockDim.x + threadIdx.x;
    if (e < E) atomicAdd(&g_cnt[dst[e]], 1);
}

__global__ void scan_kernel(int N, int E) {
    __shared__ int sums[256];
    int t = threadIdx.x;
    int chunk = (N + 255) >> 8;
    int b0 = t * chunk;
    int b1 = min(b0 + chunk, N);
    int s = 0;
    for (int i = b0; i < b1; i++) s += g_cnt[i];
    sums[t] = s;
    __syncthreads();
    for (int off = 1; off < 256; off <<= 1) {
        int v = sums[t];
        int w = (t >= off) ? sums[t - off] : 0;
        __syncthreads();
        sums[t] = v + w;
        __syncthreads();
    }
    int pref = (t > 0) ? sums[t - 1] : 0;
    for (int i = b0; i < b1; i++) {
        g_rowptr[i] = pref;
        g_cursor[i] = pref;
        g_dis[i]    = rsqrtf((float)g_cnt[i] + 1.0f);  // deg + self loop
        pref += g_cnt[i];
    }
    if (t == 0) g_rowptr[N] = E;
}

__global__ void fill_kernel(const int* __restrict__ src,
                            const int* __restrict__ dst, int E) {
    int e = blockIdx.x * blockDim.x + threadIdx.x;
    if (e < E) {
        int pos = atomicAdd(&g_cursor[dst[e]], 1);
        g_eidx[pos] = src[e];
    }
}

// zero the padded tail rows of the A (hmid) bf16 operands
__global__ void ztail_kernel(int startRow) {
    int i = blockIdx.x * blockDim.x + threadIdx.x;
    int total = (APAD_ROWS - startRow) * 128;
    if (i < total) {
        __nv_bfloat16 z = __float2bfloat16(0.f);
        g_ahi[(size_t)startRow * 128 + i] = z;
        g_alo[(size_t)startRow * 128 + i] = z;
    }
}

// transpose + bf16-split Wf[128, Nw] -> g_bhi/g_blo[n][k] (zero-padded tail)
__global__ void transb_kernel(const float* __restrict__ Wf, int Nw) {
    __shared__ float ts[64 * 129];
    int n0 = blockIdx.x * 64;
    int tid = threadIdx.x;
#pragma unroll
    for (int it = 0; it < 32; it++) {
        int idx = it * 256 + tid;
        int k  = idx >> 6;
        int nl = idx & 63;
        int gn = n0 + nl;
        float v = (gn < Nw) ? Wf[(size_t)k * Nw + gn] : 0.f;
        ts[nl * 129 + k] = v;
    }
    __syncthreads();
#pragma unroll
    for (int it = 0; it < 4; it++) {
        int idx = it * 256 + tid;
        int row = idx >> 4;
        int part = idx & 15;
        __align__(16) __nv_bfloat16 hi8[8];
        __align__(16) __nv_bfloat16 lo8[8];
#pragma unroll
        for (int j = 0; j < 8; j++) {
            float v = ts[row * 129 + part * 8 + j];
            __nv_bfloat16 h = __float2bfloat16(v);
            hi8[j] = h;
            lo8[j] = __float2bfloat16(v - __bfloat162float(h));
        }
        size_t o = (size_t)(n0 + row) * 128 + part * 8;
        *reinterpret_cast<uint4*>(&g_bhi[o]) = *reinterpret_cast<const uint4*>(hi8);
        *reinterpret_cast<uint4*>(&g_blo[o]) = *reinterpret_cast<const uint4*>(lo8);
    }
}

// ---------------- SIMT GEMM: C = epilogue(A[M,K] @ B[K,Nc]) ----------------
// MODE 0: out = (A@B) * dis[row]                 (GCN pre-aggregation)
// MODE 1: out = relu((A@B) + bias[col]); WB: also write bf16 hi/lo to g_ahi/g_alo
// MODE 2: out = sigmoid((A@B) + bias[col])       (fallback path)
template<int MODE, bool SQ, int TM, bool WB>
__global__ __launch_bounds__(256, 1)
void gemm_kernel(const float* __restrict__ Aext, int Aid,
                 const float* __restrict__ B,
                 const float* __restrict__ bias,
                 float* __restrict__ Oext, int Oid,
                 int M, int K, int Nc)
{
    const int BMv = TM * 16;
    const float* A = sel_buf(Aid, const_cast<float*>(Aext));
    float* out = sel_buf(Oid, Oext);

    __shared__ float As[TM * 16 * AST];
    __shared__ float Bs[BK * BN];

    const int tid = threadIdx.x;
    const int tx = tid & 15;
    const int ty = tid >> 4;
    const int row0 = blockIdx.y * BMv;
    const int col0 = blockIdx.x * BN;

    float2 acc[TM][8];
#pragma unroll
    for (int i = 0; i < TM; i++)
#pragma unroll
        for (int j = 0; j < 8; j++) acc[i][j] = make_float2(0.f, 0.f);

    for (int k0 = 0; k0 < K; k0 += BK) {
#pragma unroll
        for (int p = 0; p < TM / 4; p++) {
            int idx = tid + p * 256;
            int r   = idx >> 2;
            int k4  = (idx & 3) << 2;
            float4 v = make_float4(0.f, 0.f, 0.f, 0.f);
            int gr = row0 + r;
            if (gr < M) v = *reinterpret_cast<const float4*>(A + (size_t)gr * K + (k0 + k4));
            if (SQ) { v.x *= v.x; v.y *= v.y; v.z *= v.z; v.w *= v.w; }
            float* d0 = &As[r * AST + k4];
            d0[0] = v.x; d0[1] = v.y; d0[2] = v.z; d0[3] = v.w;
        }
#pragma unroll
        for (int p = 0; p < 2; p++) {
            int idx = tid + p * 256;
            int kr  = idx >> 5;
            int c4  = (idx & 31) << 2;
            float4 v = make_float4(0.f, 0.f, 0.f, 0.f);
            int gc = col0 + c4;
            if (gc < Nc) v = *reinterpret_cast<const float4*>(B + (size_t)(k0 + kr) * Nc + gc);
            *reinterpret_cast<float4*>(&Bs[kr * BN + c4]) = v;
        }
        __syncthreads();

#pragma unroll
        for (int kp = 0; kp < 8; kp++) {
            float2 a2[TM], b2[8];
#pragma unroll
            for (int i = 0; i < TM; i++)
                a2[i] = *reinterpret_cast<const float2*>(&As[(ty + 16 * i) * AST + 2 * kp]);
#pragma unroll
            for (int j = 0; j < 8; j++) {
                b2[j].x = Bs[(2 * kp)     * BN + tx + 16 * j];
                b2[j].y = Bs[(2 * kp + 1) * BN + tx + 16 * j];
            }
#pragma unroll
            for (int i = 0; i < TM; i++)
#pragma unroll
                for (int j = 0; j < 8; j++)
                    ffma2(acc[i][j], a2[i], b2[j]);
        }
        __syncthreads();
    }

    float bv[8];
    if (MODE != 0) {
#pragma unroll
        for (int j = 0; j < 8; j++) {
            int col = col0 + tx + 16 * j;
            bv[j] = (col < Nc) ? bias[col] : 0.f;
        }
    }
#pragma unroll
    for (int i = 0; i < TM; i++) {
        int row = row0 + ty + 16 * i;
        if (row >= M) continue;
        float scale = (MODE == 0) ? g_dis[row] : 1.f;
        size_t roff = (size_t)row * Nc;
#pragma unroll
        for (int j = 0; j < 8; j++) {
            int col = col0 + tx + 16 * j;
            if (col >= Nc) continue;
            float v = acc[i][j].x + acc[i][j].y;
            if (MODE == 0)      v *= scale;
            else if (MODE == 1) v = fmaxf(v + bv[j], 0.f);
            else { float t = v + bv[j]; v = 1.f / (1.f + __expf(-t)); }
            if (WB) {
                __nv_bfloat16 h = __float2bfloat16(v);
                g_ahi[roff + col] = h;
                g_alo[roff + col] = __float2bfloat16(v - __bfloat162float(h));
            } else {
                out[roff + col] = v;
            }
        }
    }
}

// ---------------- GCN aggregation: atomic-free CSR gather + finalize ----------------
__global__ void gather_kernel(const float* __restrict__ bias,
                              float* __restrict__ Oext, int Oid,
                              int N, int W, int log2wpn)
{
    float* out = sel_buf(Oid, Oext);
    int gid  = blockIdx.x * blockDim.x + threadIdx.x;
    int gw   = gid >> 5;
    int lane = gid & 31;
    int node = gw >> log2wpn;
    if (node >= N) return;
    int seg = gw & ((1 << log2wpn) - 1);
    int col = (seg << 7) | (lane << 2);

    const float* base = g_tmp + col;
    float4 acc = *reinterpret_cast<const float4*>(base + (size_t)node * W);
    int p0 = g_rowptr[node], p1 = g_rowptr[node + 1];
    for (int p = p0; p < p1; p++) {
        int s = g_eidx[p];
        float4 v = *reinterpret_cast<const float4*>(base + (size_t)s * W);
        acc.x += v.x; acc.y += v.y; acc.z += v.z; acc.w += v.w;
    }
    float d = g_dis[node];
    float4 b = *reinterpret_cast<const float4*>(bias + col);
    float4 r;
    r.x = fmaxf(fmaf(d, acc.x, b.x), 0.f);
    r.y = fmaxf(fmaf(d, acc.y, b.y), 0.f);
    r.z = fmaxf(fmaf(d, acc.z, b.z), 0.f);
    r.w = fmaxf(fmaf(d, acc.w, b.w), 0.f);
    *reinterpret_cast<float4*>(out + (size_t)node * W + col) = r;
}

// ---------------- struct GEMM via mma.sync (bf16 split, fp32 accum) ----------------
// out = sigmoid(hmid[M,128] @ Wf[128,Nw] + bf), operands pre-split into bf16 hi/lo.
// CTA tile 128x128, K=128 fully resident. smem swizzle: 16B chunk ^= (row & 7).
#define SG_AHI 0
#define SG_ALO 32768
#define SG_BHI 65536
#define SG_BLO 98304
#define SG_BIAS 131072
#define SG_SMEM (131072 + 512)

__global__ __launch_bounds__(256, 1)
void struct_gemm_mma(const float* __restrict__ bf, float* __restrict__ out,
                     int M, int Nw)
{
    extern __shared__ __align__(128) char smem[];
    const uint32_t sb = smem_to_u32(smem);
    const int tid  = threadIdx.x;
    const int lane = tid & 31;
    const int wid  = tid >> 5;
    const int wm   = wid >> 1;   // 0..3 -> 32-row band
    const int wn   = wid & 1;    // 0..1 -> 64-col band
    const int row0 = blockIdx.y * 128;
    const int col0 = blockIdx.x * 128;

    // bias tile
    if (tid < 128) {
        int gc = col0 + tid;
        float b = (gc < Nw) ? bf[gc] : 0.f;
        *reinterpret_cast<float*>(smem + SG_BIAS + tid * 4) = b;
    }

    // cp.async all 4 operand arrays, in 4 K-chunks of 32 (64B per row per chunk)
    const char* gsrc0 = (const char*)g_ahi + (size_t)row0 * 256;
    const char* gsrc1 = (const char*)g_alo + (size_t)row0 * 256;
    const char* gsrc2 = (const char*)g_bhi + (size_t)col0 * 256;
    const char* gsrc3 = (const char*)g_blo + (size_t)col0 * 256;
#pragma unroll
    for (int c = 0; c < 4; c++) {
#pragma unroll
        for (int i = 0; i < 8; i++) {
            int arr = i >> 1;                         // 0..3
            int rem = ((i & 1) << 8) + tid;           // 0..511
            int row = rem >> 2;                       // 0..127
            int part = rem & 3;
            int chunkidx = c * 4 + part;              // 16B unit in 256B row
            int sw = chunkidx ^ (row & 7);
            uint32_t dst = sb + arr * 32768 + row * 256 + sw * 16;
            const char* src = (arr == 0 ? gsrc0 : arr == 1 ? gsrc1 : arr == 2 ? gsrc2 : gsrc3)
                              + (size_t)row * 256 + chunkidx * 16;
            cp_async16(dst, src);
        }
        asm volatile("cp.async.commit_group;" ::: "memory");
    }

    float acc[2][8][4];
#pragma unroll
    for (int mt = 0; mt < 2; mt++)
#pragma unroll
        for (int nt = 0; nt < 8; nt++)
#pragma unroll
            for (int q = 0; q < 4; q++) acc[mt][nt][q] = 0.f;

    // per-thread ldmatrix row assignments
    const int arow = wm * 32 + (lane & 7) + ((lane >> 3) & 1) * 8;   // + mt*16
    const int akc  = (lane >> 4) & 1;                                // 16B k-half
    const int a7   = arow & 7;
    const int brow = wn * 64 + (lane & 7) + ((lane >> 4) & 1) * 8;   // + ntp*16
    const int bkc  = (lane >> 3) & 1;
    const int b7   = brow & 7;

#pragma unroll
    for (int c = 0; c < 4; c++) {
        if      (c == 0) asm volatile("cp.async.wait_group 3;" ::: "memory");
        else if (c == 1) asm volatile("cp.async.wait_group 2;" ::: "memory");
        else if (c == 2) asm volatile("cp.async.wait_group 1;" ::: "memory");
        else             asm volatile("cp.async.wait_group 0;" ::: "memory");
        __syncthreads();

#pragma unroll
        for (int kss = 0; kss < 2; kss++) {
            const int ks = c * 2 + kss;
            uint32_t ahi[2][4], alo[2][4], bhi[8][2], blo[8][2];
            // A fragments
#pragma unroll
            for (int mt = 0; mt < 2; mt++) {
                int row = arow + mt * 16;
                int sw = (ks * 2 + akc) ^ a7;
                uint32_t off = row * 256 + sw * 16;
                ldsm4(ahi[mt], sb + SG_AHI + off);
                ldsm4(alo[mt], sb + SG_ALO + off);
            }
            // B fragments (x4 covers 2 n-tiles)
#pragma unroll
            for (int np = 0; np < 4; np++) {
                int row = brow + np * 16;
                int sw = (ks * 2 + bkc) ^ b7;
                uint32_t off = row * 256 + sw * 16;
                uint32_t t[4];
                ldsm4(t, sb + SG_BHI + off);
                bhi[2 * np][0] = t[0]; bhi[2 * np][1] = t[1];
                bhi[2 * np + 1][0] = t[2]; bhi[2 * np + 1][1] = t[3];
                ldsm4(t, sb + SG_BLO + off);
                blo[2 * np][0] = t[0]; blo[2 * np][1] = t[1];
                blo[2 * np + 1][0] = t[2]; blo[2 * np + 1][1] = t[3];
            }
            // 3-term bf16-split accumulation
#pragma unroll
            for (int mt = 0; mt < 2; mt++)
#pragma unroll
                for (int nt = 0; nt < 8; nt++) {
                    mma_bf16(acc[mt][nt], ahi[mt], bhi[nt]);
                    mma_bf16(acc[mt][nt], ahi[mt], blo[nt]);
                    mma_bf16(acc[mt][nt], alo[mt], bhi[nt]);
                }
        }
    }

    // epilogue: bias + sigmoid + store
    const float* sbias = reinterpret_cast<const float*>(smem + SG_BIAS);
#pragma unroll
    for (int mt = 0; mt < 2; mt++) {
        int rg = row0 + wm * 32 + mt * 16 + (lane >> 2);
#pragma unroll
        for (int nt = 0; nt < 8; nt++) {
            int cl = wn * 64 + nt * 8 + (lane & 3) * 2;
            int cg = col0 + cl;
            if (cg >= Nw) continue;
            float b0 = sbias[cl], b1 = sbias[cl + 1];
            const float* a = acc[mt][nt];
            float s0 = 1.f / (1.f + __expf(-(a[0] + b0)));
            float s1 = 1.f / (1.f + __expf(-(a[1] + b1)));
            float s2 = 1.f / (1.f + __expf(-(a[2] + b0)));
            float s3 = 1.f / (1.f + __expf(-(a[3] + b1)));
            if (rg < M)
                *reinterpret_cast<float2*>(out + (size_t)rg * Nw + cg) = make_float2(s0, s1);
            if (rg + 8 < M)
                *reinterpret_cast<float2*>(out + (size_t)(rg + 8) * Nw + cg) = make_float2(s2, s3);
        }
    }
}

// ---------------- launch ----------------
extern "C" void kernel_launch(void* const* d_in, const int* in_sizes, int n_in,
                              void* d_out, int out_size)
{
    const float* x   = (const float*)d_in[0];
    const int*   ei  = (const int*)d_in[1];   // int32 on device (JAX x64 disabled)
    const float* We1 = (const float*)d_in[2];
    const float* be1 = (const float*)d_in[3];
    const float* We2 = (const float*)d_in[4];
    const float* be2 = (const float*)d_in[5];
    const float* Wd1 = (const float*)d_in[6];
    const float* bd1 = (const float*)d_in[7];
    const float* Wd2 = (const float*)d_in[8];
    const float* bd2 = (const float*)d_in[9];
    const float* Wl  = (const float*)d_in[10];
    const float* bl  = (const float*)d_in[11];
    const float* Wf  = (const float*)d_in[12];
    const float* bf  = (const float*)d_in[13];

    const int E = in_sizes[1] / 2;     // edge_index is [2, E]
    const int N = in_sizes[13];        // bf: [N]
    const int F = in_sizes[0] / N;     // x: [N, F]
    const int H = in_sizes[3];         // be1: [H]

    const int* srcp = ei;
    const int* dstp = ei + E;

    float* struct_out = (float*)d_out;                       // [N, N]
    float* xhat_out   = struct_out + (size_t)N * N;          // [N, F]
    float* z_out      = xhat_out + (size_t)N * F;            // [N, H]

    const int tb = 256;
    // CSR (deg/dis) build — shared by all 4 convs
    zero_kernel<<<(N + tb - 1) / tb, tb>>>(N);
    hist_kernel<<<(E + tb - 1) / tb, tb>>>(dstp, E);
    scan_kernel<<<1, 256>>>(N, E);
    fill_kernel<<<(E + tb - 1) / tb, tb>>>(srcp, dstp, E);

    dim3 thr(256);
    auto grid4 = [](int M, int Nc) { return dim3((Nc + BN - 1) / BN, (M + 63) / 64); };
    auto grid8 = [](int M, int Nc) { return dim3((Nc + BN - 1) / BN, (M + 127) / 128); };
    int gb128 = (N * 32 + 255) / 256;       // 1 warp / node  (W = 128)
    int gb512 = (N * 4 * 32 + 255) / 256;   // 4 warps / node (W = 512)

    const bool tc = (H == 128);
    if (tc) {
        // independent prep for the struct GEMM (can run up front)
        transb_kernel<<<(APAD_ROWS + 63) / 64, 256>>>(Wf, N);
        ztail_kernel<<<((APAD_ROWS - N) * 128 + tb - 1) / tb, tb>>>(N);
    }

    // conv1: x[N,F] @ We1 -> g_tmp -> gather -> g_h1
    gemm_kernel<0, false, 4, false><<<grid4(N, H), thr>>>(x, 0, We1, nullptr, nullptr, 1, N, F, H);
    gather_kernel<<<gb128, 256>>>(be1, nullptr, 2, N, H, 0);
    // conv2: g_h1 @ We2 -> g_tmp -> gather -> z (output)
    gemm_kernel<0, false, 4, false><<<grid4(N, H), thr>>>(nullptr, 2, We2, nullptr, nullptr, 1, N, H, H);
    gather_kernel<<<gb128, 256>>>(be2, z_out, 0, N, H, 0);
    // conv3: z @ Wd1 -> g_tmp -> gather -> g_d1
    gemm_kernel<0, false, 4, false><<<grid4(N, H), thr>>>(z_out, 0, Wd1, nullptr, nullptr, 1, N, H, H);
    gather_kernel<<<gb128, 256>>>(bd1, nullptr, 3, N, H, 0);
    // conv4: g_d1 @ Wd2 -> g_tmp -> gather -> x_hat (output)
    gemm_kernel<0, false, 8, false><<<grid8(N, F), thr>>>(nullptr, 3, Wd2, nullptr, nullptr, 1, N, H, F);
    gather_kernel<<<gb512, 256>>>(bd2, xhat_out, 0, N, F, 2);

    if (tc) {
        // hmid = relu((x_hat^2) @ Wl + bl) -> bf16 hi/lo directly (g_ahi/g_alo)
        gemm_kernel<1, true, 4, true><<<grid4(N, H), thr>>>(xhat_out, 0, Wl, bl, nullptr, 0, N, F, H);
        // struct = sigmoid(hmid @ Wf + bf) via tensor cores
        cudaFuncSetAttribute(struct_gemm_mma, cudaFuncAttributeMaxDynamicSharedMemorySize, SG_SMEM);
        dim3 gs((N + 127) / 128, (N + 127) / 128);
        struct_gemm_mma<<<gs, 256, SG_SMEM>>>(bf, struct_out, N, N);
    } else {
        // fallback: pure fp32 path
        gemm_kernel<1, true, 4, false><<<grid4(N, H), thr>>>(xhat_out, 0, Wl, bl, nullptr, 1, N, F, H);
        gemm_kernel<2, false, 8, false><<<grid8(N, N), thr>>>(nullptr, 1, Wf, bf, struct_out, 0, N, H, N);
    }
}

// round 6
// speedup vs baseline: 2.2117x; 1.4446x over previous
#include <cuda_runtime.h>
#include <cuda_bf16.h>
#include <math.h>
#include <stdint.h>

#define BN 128
#define BK 16
#define AST 18   // As row stride (words): gcd(18,32)=2 -> conflict-free pair reads

#define APAD_ROWS 10112   // 79 * 128

// ---------------- scratch (static device globals; no allocation) ----------------
__device__ __align__(256) float g_tmp [10000 * 512];  // h-hat (widest conv = 512)
__device__ __align__(256) float g_h1  [10000 * 128];
__device__ __align__(256) float g_d1  [10000 * 128];
__device__ float g_dis[10016];
__device__ int   g_cnt[10016];
__device__ int   g_rowptr[10017];
__device__ int   g_cursor[10016];
__device__ int   g_eidx[320000];
// bf16 hi/lo operands for the tensor-core struct GEMM
__device__ __align__(256) __nv_bfloat16 g_ahi[APAD_ROWS * 128];
__device__ __align__(256) __nv_bfloat16 g_alo[APAD_ROWS * 128];
__device__ __align__(256) __nv_bfloat16 g_bhi[APAD_ROWS * 128];
__device__ __align__(256) __nv_bfloat16 g_blo[APAD_ROWS * 128];

// buffer selector: 0 = external pointer, 1..3 = module-global scratch
__device__ __forceinline__ float* sel_buf(int id, float* ext) {
    switch (id) {
        case 1: return g_tmp;
        case 2: return g_h1;
        case 3: return g_d1;
        default: return ext;
    }
}

// packed fp32x2 FMA (full-rate fp32 path on sm_103a; plain FFMA-3reg is half rate)
__device__ __forceinline__ void ffma2(float2 &d, const float2 &a, const float2 &b) {
    unsigned long long du = *reinterpret_cast<unsigned long long*>(&d);
    unsigned long long au = *reinterpret_cast<const unsigned long long*>(&a);
    unsigned long long bu = *reinterpret_cast<const unsigned long long*>(&b);
    asm("fma.rn.f32x2 %0, %1, %2, %0;" : "+l"(du) : "l"(au), "l"(bu));
    d = *reinterpret_cast<float2*>(&du);
}

__device__ __forceinline__ uint32_t smem_to_u32(const void* p) {
    uint32_t a;
    asm("{ .reg .u64 t; cvta.to.shared.u64 t, %1; cvt.u32.u64 %0, t; }" : "=r"(a) : "l"(p));
    return a;
}

__device__ __forceinline__ void cp_async16(uint32_t dst, const void* src) {
    asm volatile("cp.async.cg.shared.global [%0], [%1], 16;" :: "r"(dst), "l"(src));
}

__device__ __forceinline__ void ldsm4(uint32_t* r, uint32_t addr) {
    asm volatile("ldmatrix.sync.aligned.m8n8.x4.shared.b16 {%0,%1,%2,%3}, [%4];"
                 : "=r"(r[0]), "=r"(r[1]), "=r"(r[2]), "=r"(r[3]) : "r"(addr));
}

__device__ __forceinline__ void mma_bf16(float* d, const uint32_t* a, const uint32_t* b) {
    asm volatile(
        "mma.sync.aligned.m16n8k16.row.col.f32.bf16.bf16.f32 "
        "{%0,%1,%2,%3}, {%4,%5,%6,%7}, {%8,%9}, {%0,%1,%2,%3};"
        : "+f"(d[0]), "+f"(d[1]), "+f"(d[2]), "+f"(d[3])
        : "r"(a[0]), "r"(a[1]), "r"(a[2]), "r"(a[3]), "r"(b[0]), "r"(b[1]));
}

// ---------------- CSR build ----------------
__global__ void zero_kernel(int N) {
    int i = blockIdx.x * blockDim.x + threadIdx.x;
    if (i < N) g_cnt[i] = 0;
}

__global__ void hist_kernel(const int* __restrict__ dst, int E) {
    int e = blockIdx.x * blockDim.x + threadIdx.x;
    if (e < E) atomicAdd(&g_cnt[dst[e]], 1);
}

__global__ void scan_kernel(int N, int E) {
    __shared__ int sums[256];
    int t = threadIdx.x;
    int chunk = (N + 255) >> 8;
    int b0 = t * chunk;
    int b1 = min(b0 + chunk, N);
    int s = 0;
    for (int i = b0; i < b1; i++) s += g_cnt[i];
    sums[t] = s;
    __syncthreads();
    for (int off = 1; off < 256; off <<= 1) {
        int v = sums[t];
        int w = (t >= off) ? sums[t - off] : 0;
        __syncthreads();
        sums[t] = v + w;
        __syncthreads();
    }
    int pref = (t > 0) ? sums[t - 1] : 0;
    for (int i = b0; i < b1; i++) {
        g_rowptr[i] = pref;
        g_cursor[i] = pref;
        g_dis[i]    = rsqrtf((float)g_cnt[i] + 1.0f);  // deg + self loop
        pref += g_cnt[i];
    }
    if (t == 0) g_rowptr[N] = E;
}

__global__ void fill_kernel(const int* __restrict__ src,
                            const int* __restrict__ dst, int E) {
    int e = blockIdx.x * blockDim.x + threadIdx.x;
    if (e < E) {
        int pos = atomicAdd(&g_cursor[dst[e]], 1);
        g_eidx[pos] = src[e];
    }
}

// zero the padded tail rows of the A (hmid) bf16 operands
__global__ void ztail_kernel(int startRow) {
    int i = blockIdx.x * blockDim.x + threadIdx.x;
    int total = (APAD_ROWS - startRow) * 128;
    if (i < total) {
        __nv_bfloat16 z = __float2bfloat16(0.f);
        g_ahi[(size_t)startRow * 128 + i] = z;
        g_alo[(size_t)startRow * 128 + i] = z;
    }
}

// transpose + bf16-split Wf[128, Nw] -> g_bhi/g_blo[n][k] (zero-padded tail)
__global__ void transb_kernel(const float* __restrict__ Wf, int Nw) {
    __shared__ float ts[64 * 129];
    int n0 = blockIdx.x * 64;
    int tid = threadIdx.x;
#pragma unroll
    for (int it = 0; it < 32; it++) {
        int idx = it * 256 + tid;
        int k  = idx >> 6;
        int nl = idx & 63;
        int gn = n0 + nl;
        float v = (gn < Nw) ? Wf[(size_t)k * Nw + gn] : 0.f;
        ts[nl * 129 + k] = v;
    }
    __syncthreads();
#pragma unroll
    for (int it = 0; it < 4; it++) {
        int idx = it * 256 + tid;
        int row = idx >> 4;
        int part = idx & 15;
        __align__(16) __nv_bfloat16 hi8[8];
        __align__(16) __nv_bfloat16 lo8[8];
#pragma unroll
        for (int j = 0; j < 8; j++) {
            float v = ts[row * 129 + part * 8 + j];
            __nv_bfloat16 h = __float2bfloat16(v);
            hi8[j] = h;
            lo8[j] = __float2bfloat16(v - __bfloat162float(h));
        }
        size_t o = (size_t)(n0 + row) * 128 + part * 8;
        *reinterpret_cast<uint4*>(&g_bhi[o]) = *reinterpret_cast<const uint4*>(hi8);
        *reinterpret_cast<uint4*>(&g_blo[o]) = *reinterpret_cast<const uint4*>(lo8);
    }
}

// ---------------- SIMT GEMM: C = epilogue(A[M,K] @ B[K,Nc]) ----------------
// MODE 0: out = (A@B) * dis[row]                 (GCN pre-aggregation)
// MODE 1: out = relu((A@B) + bias[col]); WB: also write bf16 hi/lo to g_ahi/g_alo
// MODE 2: out = sigmoid((A@B) + bias[col])       (fallback path)
template<int MODE, bool SQ, int TM, bool WB>
__global__ __launch_bounds__(256, 1)
void gemm_kernel(const float* __restrict__ Aext, int Aid,
                 const float* __restrict__ B,
                 const float* __restrict__ bias,
                 float* __restrict__ Oext, int Oid,
                 int M, int K, int Nc)
{
    const int BMv = TM * 16;
    const float* A = sel_buf(Aid, const_cast<float*>(Aext));
    float* out = sel_buf(Oid, Oext);

    __shared__ float As[TM * 16 * AST];
    __shared__ float Bs[BK * BN];

    const int tid = threadIdx.x;
    const int tx = tid & 15;
    const int ty = tid >> 4;
    const int row0 = blockIdx.y * BMv;
    const int col0 = blockIdx.x * BN;

    float2 acc[TM][8];
#pragma unroll
    for (int i = 0; i < TM; i++)
#pragma unroll
        for (int j = 0; j < 8; j++) acc[i][j] = make_float2(0.f, 0.f);

    for (int k0 = 0; k0 < K; k0 += BK) {
#pragma unroll
        for (int p = 0; p < TM / 4; p++) {
            int idx = tid + p * 256;
            int r   = idx >> 2;
            int k4  = (idx & 3) << 2;
            float4 v = make_float4(0.f, 0.f, 0.f, 0.f);
            int gr = row0 + r;
            if (gr < M) v = *reinterpret_cast<const float4*>(A + (size_t)gr * K + (k0 + k4));
            if (SQ) { v.x *= v.x; v.y *= v.y; v.z *= v.z; v.w *= v.w; }
            float* d0 = &As[r * AST + k4];
            d0[0] = v.x; d0[1] = v.y; d0[2] = v.z; d0[3] = v.w;
        }
#pragma unroll
        for (int p = 0; p < 2; p++) {
            int idx = tid + p * 256;
            int kr  = idx >> 5;
            int c4  = (idx & 31) << 2;
            float4 v = make_float4(0.f, 0.f, 0.f, 0.f);
            int gc = col0 + c4;
            if (gc < Nc) v = *reinterpret_cast<const float4*>(B + (size_t)(k0 + kr) * Nc + gc);
            *reinterpret_cast<float4*>(&Bs[kr * BN + c4]) = v;
        }
        __syncthreads();

#pragma unroll
        for (int kp = 0; kp < 8; kp++) {
            float2 a2[TM], b2[8];
#pragma unroll
            for (int i = 0; i < TM; i++)
                a2[i] = *reinterpret_cast<const float2*>(&As[(ty + 16 * i) * AST + 2 * kp]);
#pragma unroll
            for (int j = 0; j < 8; j++) {
                b2[j].x = Bs[(2 * kp)     * BN + tx + 16 * j];
                b2[j].y = Bs[(2 * kp + 1) * BN + tx + 16 * j];
            }
#pragma unroll
            for (int i = 0; i < TM; i++)
#pragma unroll
                for (int j = 0; j < 8; j++)
                    ffma2(acc[i][j], a2[i], b2[j]);
        }
        __syncthreads();
    }

    float bv[8];
    if (MODE != 0) {
#pragma unroll
        for (int j = 0; j < 8; j++) {
            int col = col0 + tx + 16 * j;
            bv[j] = (col < Nc) ? bias[col] : 0.f;
        }
    }
#pragma unroll
    for (int i = 0; i < TM; i++) {
        int row = row0 + ty + 16 * i;
        if (row >= M) continue;
        float scale = (MODE == 0) ? g_dis[row] : 1.f;
        size_t roff = (size_t)row * Nc;
#pragma unroll
        for (int j = 0; j < 8; j++) {
            int col = col0 + tx + 16 * j;
            if (col >= Nc) continue;
            float v = acc[i][j].x + acc[i][j].y;
            if (MODE == 0)      v *= scale;
            else if (MODE == 1) v = fmaxf(v + bv[j], 0.f);
            else { float t = v + bv[j]; v = __fdividef(1.f, 1.f + __expf(-t)); }
            if (WB) {
                __nv_bfloat16 h = __float2bfloat16(v);
                g_ahi[roff + col] = h;
                g_alo[roff + col] = __float2bfloat16(v - __bfloat162float(h));
            } else {
                out[roff + col] = v;
            }
        }
    }
}

// ---------------- GCN aggregation: atomic-free CSR gather ----------------
// GMODE 0: out = relu(dis*acc + bias)           (standard conv finalize)
// GMODE 1: out = relu(dis*acc + bias) * dis     (conv3: pre-scale for commuted conv4)
// GMODE 2: out = dis*acc                        (conv4 pre-aggregation, no bias/relu)
template<int GMODE>
__global__ void gather_kernel(const float* __restrict__ bias,
                              float* __restrict__ Oext, int Oid, int Iid,
                              int N, int W, int log2wpn)
{
    const float* in = sel_buf(Iid, nullptr);
    float* out = sel_buf(Oid, Oext);
    int gid  = blockIdx.x * blockDim.x + threadIdx.x;
    int gw   = gid >> 5;
    int lane = gid & 31;
    int node = gw >> log2wpn;
    if (node >= N) return;
    int seg = gw & ((1 << log2wpn) - 1);
    int col = (seg << 7) | (lane << 2);

    const float* base = in + col;
    float4 acc = *reinterpret_cast<const float4*>(base + (size_t)node * W);
    int p0 = g_rowptr[node], p1 = g_rowptr[node + 1];
    for (int p = p0; p < p1; p++) {
        int s = g_eidx[p];
        float4 v = *reinterpret_cast<const float4*>(base + (size_t)s * W);
        acc.x += v.x; acc.y += v.y; acc.z += v.z; acc.w += v.w;
    }
    float d = g_dis[node];
    float4 r;
    if (GMODE == 2) {
        r.x = d * acc.x; r.y = d * acc.y; r.z = d * acc.z; r.w = d * acc.w;
    } else {
        float4 b = *reinterpret_cast<const float4*>(bias + col);
        r.x = fmaxf(fmaf(d, acc.x, b.x), 0.f);
        r.y = fmaxf(fmaf(d, acc.y, b.y), 0.f);
        r.z = fmaxf(fmaf(d, acc.z, b.z), 0.f);
        r.w = fmaxf(fmaf(d, acc.w, b.w), 0.f);
        if (GMODE == 1) { r.x *= d; r.y *= d; r.z *= d; r.w *= d; }
    }
    *reinterpret_cast<float4*>(out + (size_t)node * W + col) = r;
}

// ---------------- struct GEMM via mma.sync (bf16 split, fp32 accum) ----------------
// out = sigmoid(hmid[M,128] @ Wf[128,Nw] + bf), operands pre-split into bf16 hi/lo.
// CTA tile 128x128; K processed in 4 chunks of 32, double-buffered cp.async;
// 2 CTAs/SM so loads/epilogue of one CTA overlap HMMA of the other.
// smem per buffer: AHI/ALO/BHI/BLO, each 128 rows x 64 B; swizzle q ^= (row>>1)&3.
#define SGB 32768            // bytes per double-buffer slot (4 arrays x 8 KB)
#define SG_BIAS 65536
#define SG_SMEM (65536 + 512)

__device__ __forceinline__ void sg_issue_chunk(
    uint32_t sb, int buf, int c, int tid,
    const char* a0, const char* a1, const char* a2, const char* a3)
{
#pragma unroll
    for (int i = 0; i < 8; i++) {
        int arr = i >> 1;                       // 0..3
        int rem = ((i & 1) << 8) + tid;         // 0..511
        int row = rem >> 2;                     // 0..127
        int q   = rem & 3;                      // 16B unit within 64B row
        int sw  = q ^ ((row >> 1) & 3);
        uint32_t dst = sb + buf * SGB + arr * 8192 + row * 64 + sw * 16;
        const char* base = (arr == 0) ? a0 : (arr == 1) ? a1 : (arr == 2) ? a2 : a3;
        cp_async16(dst, base + (size_t)row * 256 + c * 64 + q * 16);
    }
    asm volatile("cp.async.commit_group;" ::: "memory");
}

__global__ __launch_bounds__(256, 2)
void struct_gemm_mma(const float* __restrict__ bf, float* __restrict__ out,
                     int M, int Nw)
{
    extern __shared__ __align__(128) char smem[];
    const uint32_t sb = smem_to_u32(smem);
    const int tid  = threadIdx.x;
    const int lane = tid & 31;
    const int wid  = tid >> 5;
    const int wm   = wid >> 1;
    const int wn   = wid & 1;
    const int row0 = blockIdx.y * 128;
    const int col0 = blockIdx.x * 128;

    if (tid < 128) {
        int gc = col0 + tid;
        *reinterpret_cast<float*>(smem + SG_BIAS + tid * 4) = (gc < Nw) ? bf[gc] : 0.f;
    }

    const char* a0 = (const char*)g_ahi + (size_t)row0 * 256;
    const char* a1 = (const char*)g_alo + (size_t)row0 * 256;
    const char* a2 = (const char*)g_bhi + (size_t)col0 * 256;
    const char* a3 = (const char*)g_blo + (size_t)col0 * 256;

    sg_issue_chunk(sb, 0, 0, tid, a0, a1, a2, a3);
    sg_issue_chunk(sb, 1, 1, tid, a0, a1, a2, a3);

    float acc[2][8][4] = {};

    const int arow = wm * 32 + (lane & 7) + ((lane >> 3) & 1) * 8;
    const int akc  = (lane >> 4) & 1;
    const int brow = wn * 64 + (lane & 7) + ((lane >> 4) & 1) * 8;
    const int bkc  = (lane >> 3) & 1;

#pragma unroll
    for (int c = 0; c < 4; c++) {
        if (c < 3) asm volatile("cp.async.wait_group 1;" ::: "memory");
        else       asm volatile("cp.async.wait_group 0;" ::: "memory");
        __syncthreads();
        const uint32_t bb = sb + (c & 1) * SGB;
#pragma unroll
        for (int ks = 0; ks < 2; ks++) {
            uint32_t ahi[2][4], alo[2][4];
#pragma unroll
            for (int mt = 0; mt < 2; mt++) {
                int r = arow + mt * 16;
                int sw = (ks * 2 + akc) ^ ((r >> 1) & 3);
                ldsm4(ahi[mt], bb + 0    + r * 64 + sw * 16);
                ldsm4(alo[mt], bb + 8192 + r * 64 + sw * 16);
            }
#pragma unroll
            for (int g = 0; g < 2; g++) {
                uint32_t bhi[4][2], blo[4][2];
#pragma unroll
                for (int np = 0; np < 2; np++) {
                    int r = brow + (g * 2 + np) * 16;
                    int sw = (ks * 2 + bkc) ^ ((r >> 1) & 3);
                    uint32_t t[4];
                    ldsm4(t, bb + 16384 + r * 64 + sw * 16);
                    bhi[np*2][0] = t[0]; bhi[np*2][1] = t[1];
                    bhi[np*2+1][0] = t[2]; bhi[np*2+1][1] = t[3];
                    ldsm4(t, bb + 24576 + r * 64 + sw * 16);
                    blo[np*2][0] = t[0]; blo[np*2][1] = t[1];
                    blo[np*2+1][0] = t[2]; blo[np*2+1][1] = t[3];
                }
#pragma unroll
                for (int mt = 0; mt < 2; mt++)
#pragma unroll
                    for (int j = 0; j < 4; j++) {
                        float* d = acc[mt][g * 4 + j];
                        mma_bf16(d, ahi[mt], bhi[j]);
                        mma_bf16(d, ahi[mt], blo[j]);
                        mma_bf16(d, alo[mt], bhi[j]);
                    }
            }
        }
        __syncthreads();
        if (c < 2) sg_issue_chunk(sb, c & 1, c + 2, tid, a0, a1, a2, a3);
    }

    // epilogue: bias + sigmoid + store
    const float* sbias = reinterpret_cast<const float*>(smem + SG_BIAS);
#pragma unroll
    for (int mt = 0; mt < 2; mt++) {
        int rg = row0 + wm * 32 + mt * 16 + (lane >> 2);
#pragma unroll
        for (int nt = 0; nt < 8; nt++) {
            int cl = wn * 64 + nt * 8 + (lane & 3) * 2;
            int cg = col0 + cl;
            if (cg >= Nw) continue;
            float b0 = sbias[cl], b1 = sbias[cl + 1];
            const float* a = acc[mt][nt];
            float s0 = __fdividef(1.f, 1.f + __expf(-(a[0] + b0)));
            float s1 = __fdividef(1.f, 1.f + __expf(-(a[1] + b1)));
            float s2 = __fdividef(1.f, 1.f + __expf(-(a[2] + b0)));
            float s3 = __fdividef(1.f, 1.f + __expf(-(a[3] + b1)));
            if (rg < M)
                *reinterpret_cast<float2*>(out + (size_t)rg * Nw + cg) = make_float2(s0, s1);
            if (rg + 8 < M)
                *reinterpret_cast<float2*>(out + (size_t)(rg + 8) * Nw + cg) = make_float2(s2, s3);
        }
    }
}

// ---------------- launch ----------------
extern "C" void kernel_launch(void* const* d_in, const int* in_sizes, int n_in,
                              void* d_out, int out_size)
{
    const float* x   = (const float*)d_in[0];
    const int*   ei  = (const int*)d_in[1];   // int32 on device (JAX x64 disabled)
    const float* We1 = (const float*)d_in[2];
    const float* be1 = (const float*)d_in[3];
    const float* We2 = (const float*)d_in[4];
    const float* be2 = (const float*)d_in[5];
    const float* Wd1 = (const float*)d_in[6];
    const float* bd1 = (const float*)d_in[7];
    const float* Wd2 = (const float*)d_in[8];
    const float* bd2 = (const float*)d_in[9];
    const float* Wl  = (const float*)d_in[10];
    const float* bl  = (const float*)d_in[11];
    const float* Wf  = (const float*)d_in[12];
    const float* bf  = (const float*)d_in[13];

    const int E = in_sizes[1] / 2;     // edge_index is [2, E]
    const int N = in_sizes[13];        // bf: [N]
    const int F = in_sizes[0] / N;     // x: [N, F]
    const int H = in_sizes[3];         // be1: [H]

    const int* srcp = ei;
    const int* dstp = ei + E;

    float* struct_out = (float*)d_out;                       // [N, N]
    float* xhat_out   = struct_out + (size_t)N * N;          // [N, F]
    float* z_out      = xhat_out + (size_t)N * F;            // [N, H]

    const int tb = 256;
    // CSR (deg/dis) build — shared by all 4 convs
    zero_kernel<<<(N + tb - 1) / tb, tb>>>(N);
    hist_kernel<<<(E + tb - 1) / tb, tb>>>(dstp, E);
    scan_kernel<<<1, 256>>>(N, E);
    fill_kernel<<<(E + tb - 1) / tb, tb>>>(srcp, dstp, E);

    dim3 thr(256);
    auto grid4 = [](int M, int Nc) { return dim3((Nc + BN - 1) / BN, (M + 63) / 64); };
    auto grid8 = [](int M, int Nc) { return dim3((Nc + BN - 1) / BN, (M + 127) / 128); };
    int gb128 = (N * 32 + 255) / 256;       // 1 warp / node  (W = 128)
    int gb512 = (N * 4 * 32 + 255) / 256;   // 4 warps / node (W = 512)

    const bool tc = (H == 128);
    if (tc) {
        // independent prep for the struct GEMM (can run up front)
        transb_kernel<<<(APAD_ROWS + 63) / 64, 256>>>(Wf, N);
        ztail_kernel<<<((APAD_ROWS - N) * 128 + tb - 1) / tb, tb>>>(N);
    }

    // conv1: x[N,F] @ We1 -> g_tmp -> gather -> g_h1
    gemm_kernel<0, false, 4, false><<<grid4(N, H), thr>>>(x, 0, We1, nullptr, nullptr, 1, N, F, H);
    gather_kernel<0><<<gb128, 256>>>(be1, nullptr, 2, 1, N, H, 0);
    // conv2: g_h1 @ We2 -> g_tmp -> gather -> z (output)
    gemm_kernel<0, false, 4, false><<<grid4(N, H), thr>>>(nullptr, 2, We2, nullptr, nullptr, 1, N, H, H);
    gather_kernel<0><<<gb128, 256>>>(be2, z_out, 0, 1, N, H, 0);
    // conv3: z @ Wd1 -> g_tmp -> gather -> g_d1 (pre-scaled by dis for commuted conv4)
    gemm_kernel<0, false, 4, false><<<grid4(N, H), thr>>>(z_out, 0, Wd1, nullptr, nullptr, 1, N, H, H);

    if (tc) {
        gather_kernel<1><<<gb128, 256>>>(bd1, nullptr, 3, 1, N, H, 0);
        // conv4 (commuted): pre-aggregate d1 (128-wide), then GEMM with fused relu+bias
        gather_kernel<2><<<gb128, 256>>>(nullptr, nullptr, 2, 3, N, H, 0);   // g_d1 -> g_h1
        gemm_kernel<1, false, 4, false><<<grid4(N, F), thr>>>(nullptr, 2, Wd2, bd2, xhat_out, 0, N, H, F);
        // hmid = relu((x_hat^2) @ Wl + bl) -> bf16 hi/lo directly (g_ahi/g_alo)
        gemm_kernel<1, true, 4, true><<<grid4(N, H), thr>>>(xhat_out, 0, Wl, bl, nullptr, 0, N, F, H);
        // struct = sigmoid(hmid @ Wf + bf) via tensor cores
        cudaFuncSetAttribute(struct_gemm_mma, cudaFuncAttributeMaxDynamicSharedMemorySize, SG_SMEM);
        dim3 gs((N + 127) / 128, (N + 127) / 128);
        struct_gemm_mma<<<gs, 256, SG_SMEM>>>(bf, struct_out, N, N);
    } else {
        // fallback: pure fp32 path, original conv4 order
        gather_kernel<0><<<gb128, 256>>>(bd1, nullptr, 3, 1, N, H, 0);
        gemm_kernel<0, false, 8, false><<<grid8(N, F), thr>>>(nullptr, 3, Wd2, nullptr, nullptr, 1, N, H, F);
        gather_kernel<0><<<gb512, 256>>>(bd2, xhat_out, 0, 1, N, F, 2);
        gemm_kernel<1, true, 4, false><<<grid4(N, H), thr>>>(xhat_out, 0, Wl, bl, nullptr, 1, N, F, H);
        gemm_kernel<2, false, 8, false><<<grid8(N, N), thr>>>(nullptr, 1, Wf, bf, struct_out, 0, N, H, N);
    }
}